// round 7
// baseline (speedup 1.0000x reference)
#include <cuda_runtime.h>
#include <math.h>

typedef unsigned long long ull;
#define NCTA 128
#define TPB  512

// ---- device scratch (static; allocations forbidden) ----
__device__ float g_u[512u*1024u*64u];   // u[t][d][b]
__device__ float g_s[512u*1024u*64u];   // states[t][d][b]
__device__ float g_x[2][1024*64];       // state ping-pong, layout [k][b]
__device__ ull   g_part[8u*1024u*32u];  // partials [j][d][bp] (f32x2 over batch pair)
__device__ int   g_len[64];
__device__ unsigned g_cnt[16];          // per-d-group arrival counters
__device__ unsigned g_bar_count;
__device__ unsigned g_bar_gen;

// ---- packed f32x2 helpers ----
__device__ __forceinline__ ull pack2(float a, float b){ ull r; asm("mov.b64 %0,{%1,%2};":"=l"(r):"f"(a),"f"(b)); return r; }
__device__ __forceinline__ float2 unpk(ull v){ float2 r; asm("mov.b64 {%0,%1},%2;":"=f"(r.x),"=f"(r.y):"l"(v)); return r; }
__device__ __forceinline__ ull ffma2(ull a, ull b, ull c){ ull d; asm("fma.rn.f32x2 %0,%1,%2,%3;":"=l"(d):"l"(a),"l"(b),"l"(c)); return d; }
__device__ __forceinline__ ull add2(ull a, ull b){ ull d; asm("add.rn.f32x2 %0,%1,%2;":"=l"(d):"l"(a),"l"(b)); return d; }

// ---- init: x0 broadcast ([k][b]); zero lengths + counters ----
__global__ void init_kernel(const float* __restrict__ x0) {
    int idx = blockIdx.x * 256 + threadIdx.x;
    g_x[0][idx] = x0[idx >> 6];
    if (idx < 64) g_len[idx] = 0;
    if (idx < 16) g_cnt[idx] = 0u;
}

// ---- lengths ----
__global__ void len_kernel(const float* __restrict__ emb) {
    int t = blockIdx.x;
    int b = threadIdx.x >> 2, p = threadIdx.x & 3;
    const float* row = emb + ((size_t)t*64 + b)*300;
    float s = 0.f;
    for (int i = p; i < 300; i += 4) s += row[i];
    s += __shfl_xor_sync(0xffffffffu, s, 1);
    s += __shfl_xor_sync(0xffffffffu, s, 2);
    if (p == 0 && s != 0.f) atomicAdd(&g_len[b], 1);
}

// ---- projection: 2 timesteps per block; W tile loaded once per pair ----
__global__ __launch_bounds__(256) void proj_kernel(const float* __restrict__ emb,
                                                   const float* __restrict__ win,
                                                   const float* __restrict__ bias) {
    __align__(16) __shared__ float Es[2][32][66];
    __align__(16) __shared__ ull   Wd[32][64];
    const int tid = threadIdx.x;
    const int tx = tid & 15;
    const int ty = tid >> 4;
    const int t0 = blockIdx.y * 2;
    const int d0 = blockIdx.x * 64;
    const int lb = tid >> 2, lq = tid & 3;

    ull acc[2][4][2];
    #pragma unroll
    for (int h = 0; h < 2; ++h)
        #pragma unroll
        for (int i = 0; i < 4; ++i) { acc[h][i][0] = 0ull; acc[h][i][1] = 0ull; }

    for (int k0 = 0; k0 < 300; k0 += 32) {
        #pragma unroll
        for (int j = 0; j < 8; ++j) {
            int kk = lq*8 + j, k = k0 + kk;
            bool ok = (k < 300);
            Es[0][kk][lb] = ok ? emb[((size_t)t0*64 + lb)*300 + k] : 0.f;
            Es[1][kk][lb] = ok ? emb[((size_t)(t0+1)*64 + lb)*300 + k] : 0.f;
            float w = ok ? win[((size_t)(d0 + lb))*300 + k] : 0.f;
            Wd[kk][lb] = pack2(w, w);
        }
        __syncthreads();
        #pragma unroll
        for (int kk = 0; kk < 32; ++kk) {
            ulonglong2 wA = *(const ulonglong2*)&Wd[kk][ty*4];
            ulonglong2 wB = *(const ulonglong2*)&Wd[kk][ty*4 + 2];
            #pragma unroll
            for (int h = 0; h < 2; ++h) {
                ull e01 = *(const ull*)&Es[h][kk][tx*4];
                ull e23 = *(const ull*)&Es[h][kk][tx*4 + 2];
                acc[h][0][0] = ffma2(e01, wA.x, acc[h][0][0]); acc[h][0][1] = ffma2(e23, wA.x, acc[h][0][1]);
                acc[h][1][0] = ffma2(e01, wA.y, acc[h][1][0]); acc[h][1][1] = ffma2(e23, wA.y, acc[h][1][1]);
                acc[h][2][0] = ffma2(e01, wB.x, acc[h][2][0]); acc[h][2][1] = ffma2(e23, wB.x, acc[h][2][1]);
                acc[h][3][0] = ffma2(e01, wB.y, acc[h][3][0]); acc[h][3][1] = ffma2(e23, wB.y, acc[h][3][1]);
            }
        }
        __syncthreads();
    }
    #pragma unroll
    for (int h = 0; h < 2; ++h)
        #pragma unroll
        for (int dd = 0; dd < 4; ++dd) {
            int d = d0 + ty*4 + dd;
            float bb = bias[d];
            float2 p0 = unpk(acc[h][dd][0]), p1 = unpk(acc[h][dd][1]);
            float4 o = make_float4(p0.x + bb, p0.y + bb, p1.x + bb, p1.y + bb);
            *(float4*)&g_u[((size_t)(t0+h)*1024 + d)*64 + tx*4] = o;
        }
}

// ---- grid barrier ----
__device__ __forceinline__ void grid_barrier() {
    __syncthreads();
    if (threadIdx.x == 0) {
        unsigned gen;
        asm volatile("ld.acquire.gpu.global.u32 %0, [%1];" : "=r"(gen) : "l"(&g_bar_gen));
        unsigned prev;
        asm volatile("atom.acq_rel.gpu.global.add.u32 %0, [%1], 1;" : "=r"(prev) : "l"(&g_bar_count));
        if (prev == NCTA - 1u) {
            asm volatile("st.relaxed.gpu.global.u32 [%0], %1;" :: "l"(&g_bar_count), "r"(0u));
            asm volatile("st.release.gpu.global.u32 [%0], %1;" :: "l"(&g_bar_gen), "r"(gen + 1u));
        } else {
            unsigned g2;
            do {
                asm volatile("ld.acquire.gpu.global.u32 %0, [%1];" : "=r"(g2) : "l"(&g_bar_gen));
            } while (g2 == gen);
        }
    }
    __syncthreads();
}

// ---- persistent scan: 2-D split (16 d-groups x 8 k-slices) ----
// CTA s: i = s>>3 (d rows 64i..64i+63), j = s&7 (k 128j..128j+127).
// Phase 1 thread: bq = tid&15 (batches 4bq..+3), rp = tid>>4 (rows 2rp, 2rp+1 local).
// Phase 2 (tid<256): dl = tid>>5, bp = tid&31 -> global row dg = 8s+dl, batches 2bp, 2bp+1.
__global__ __launch_bounds__(TPB, 1) void scan_kernel(const float* __restrict__ layer_w,
                                                      const float* __restrict__ init_state) {
    extern __shared__ __align__(16) unsigned char dsm[];
    ulonglong2* wsm = (ulonglong2*)dsm;            // [128 k][32 rp] = 65536 B
    ulonglong2* xsm = wsm + 4096;                  // [128 k][16 bq] = 32768 B

    const int tid = threadIdx.x;
    const int s   = blockIdx.x;
    const int i   = s >> 3, j = s & 7;
    const int bq  = tid & 15;
    const int rp  = tid >> 4;                      // 0..31

    // W slice fill (once): wsm[k][rq] = ((w[2rq,k],w[2rq,k]), (w[2rq+1,k],w[2rq+1,k]))
    for (int e = tid; e < 4096; e += TPB) {
        int k = e & 127, rq = e >> 7;
        float w0 = layer_w[(size_t)(i*64 + 2*rq    )*1024 + j*128 + k];
        float w1 = layer_w[(size_t)(i*64 + 2*rq + 1)*1024 + j*128 + k];
        wsm[(size_t)k*32 + rq] = make_ulonglong2(pack2(w0, w0), pack2(w1, w1));
    }

    // phase-2 role state
    const int dl = tid >> 5, bp = tid & 31;        // dl 0..15 (only <8 used)
    const int dg = 8*s + (dl & 7);
    float xo0 = init_state[dg], xo1 = init_state[dg];
    int len0 = 0, len1 = 0;
    if (tid < 256) { len0 = g_len[2*bp]; len1 = g_len[2*bp + 1]; }

    __syncthreads();

    for (int t = 0; t < 512; ++t) {
        const float* xin = g_x[t & 1];

        // prefetch u for phase-2 role (DRAM latency hidden behind phase 1)
        ull upre = 0ull;
        if (tid < 256) upre = __ldcg((const ull*)&g_u[((size_t)t*1024 + dg)*64 + 2*bp]);

        // stage x slice (32 KB): coalesced, L1-bypassing
        {
            const ulonglong2* src = (const ulonglong2*)(xin + j * 8192);
            #pragma unroll
            for (int p = 0; p < 4; ++p)
                xsm[tid + p*512] = __ldcg(src + tid + p*512);
        }
        __syncthreads();

        // core: 128 k x (2 rows x 2 batch-pairs)
        ull a00 = 0ull, a01 = 0ull, a10 = 0ull, a11 = 0ull;
        const ulonglong2* wk = wsm + rp;
        const ulonglong2* xk = xsm + bq;
        #pragma unroll 8
        for (int k = 0; k < 128; ++k) {
            ulonglong2 w  = wk[(size_t)k*32];
            ulonglong2 xv = xk[(size_t)k*16];
            a00 = ffma2(xv.x, w.x, a00); a01 = ffma2(xv.y, w.x, a01);
            a10 = ffma2(xv.x, w.y, a10); a11 = ffma2(xv.y, w.y, a11);
        }

        // partial store: [j][d][bp]
        ull* pb = g_part + ((size_t)j*1024 + i*64 + 2*rp)*32 + 2*bq;
        *(ulonglong2*)pb        = make_ulonglong2(a00, a01);
        *(ulonglong2*)(pb + 32) = make_ulonglong2(a10, a11);
        __syncthreads();

        if (tid == 0) {
            asm volatile("red.release.gpu.global.add.u32 [%0], %1;" :: "l"(&g_cnt[i]), "r"(1u));
            unsigned target = 8u * (unsigned)(t + 1), c;
            do {
                asm volatile("ld.acquire.gpu.global.u32 %0, [%1];" : "=r"(c) : "l"(&g_cnt[i]));
            } while (c < target);
        }
        __syncthreads();

        // phase 2: reduce 8 partials, activate, write next state + states
        if (tid < 256) {
            ull p0 = __ldcg(&g_part[((size_t)0*1024 + dg)*32 + bp]);
            ull p1 = __ldcg(&g_part[((size_t)1*1024 + dg)*32 + bp]);
            ull p2 = __ldcg(&g_part[((size_t)2*1024 + dg)*32 + bp]);
            ull p3 = __ldcg(&g_part[((size_t)3*1024 + dg)*32 + bp]);
            ull p4 = __ldcg(&g_part[((size_t)4*1024 + dg)*32 + bp]);
            ull p5 = __ldcg(&g_part[((size_t)5*1024 + dg)*32 + bp]);
            ull p6 = __ldcg(&g_part[((size_t)6*1024 + dg)*32 + bp]);
            ull p7 = __ldcg(&g_part[((size_t)7*1024 + dg)*32 + bp]);
            ull ssum = add2(add2(add2(p0, p1), add2(p2, p3)),
                            add2(add2(p4, p5), add2(p6, p7)));
            ssum = add2(ssum, upre);

            float2 a = unpk(ssum);
            float n0 = 0.5f * tanhf(a.x) + 0.5f * xo0;
            float n1 = 0.5f * tanhf(a.y) + 0.5f * xo1;
            if (t >= len0) n0 = 0.f;
            if (t >= len1) n1 = 0.f;
            xo0 = n0; xo1 = n1;

            __stcg((float2*)(g_x[(t & 1) ^ 1] + (size_t)dg*64 + 2*bp), make_float2(n0, n1));
            *(float2*)&g_s[((size_t)t*1024 + dg)*64 + 2*bp] = make_float2(n0, n1);
        }
        grid_barrier();
    }
}

// ---- transpose g_s[t][d][b] -> out[b][t][d] ----
__global__ __launch_bounds__(256) void trans_kernel(float* __restrict__ out) {
    __shared__ float ts[64][65];
    const int t  = blockIdx.y;
    const int d0 = blockIdx.x * 64;
    const int tid = threadIdx.x;
    #pragma unroll
    for (int j = 0; j < 16; ++j) {
        int idx = j*256 + tid;
        int dl = idx >> 6, b = idx & 63;
        ts[dl][b] = g_s[(((size_t)t << 10) + d0 + dl)*64 + b];
    }
    __syncthreads();
    #pragma unroll
    for (int j = 0; j < 16; ++j) {
        int idx = j*256 + tid;
        int b = idx >> 6, dl = idx & 63;
        out[((size_t)b*512 + t)*1024 + d0 + dl] = ts[dl][b];
    }
}

__global__ void tail_kernel(float* out) {
    int b = threadIdx.x;
    if (b < 64) out[33554432u + b] = (float)g_len[b];
}

extern "C" void kernel_launch(void* const* d_in, const int* in_sizes, int n_in,
                              void* d_out, int out_size) {
    const float* emb  = (const float*)d_in[0];
    const float* win  = (const float*)d_in[1];
    const float* lw   = (const float*)d_in[2];
    const float* bias = (const float*)d_in[3];
    const float* x0   = (const float*)d_in[4];
    float* out = (float*)d_out;

    static int smem_set = 0;
    if (!smem_set) {
        cudaFuncSetAttribute(scan_kernel, cudaFuncAttributeMaxDynamicSharedMemorySize, 98304);
        smem_set = 1;
    }

    init_kernel<<<256, 256>>>(x0);
    len_kernel<<<512, 256>>>(emb);
    proj_kernel<<<dim3(16, 256), 256>>>(emb, win, bias);
    scan_kernel<<<NCTA, TPB, 98304>>>(lw, x0);
    trans_kernel<<<dim3(16, 512), 256>>>(out);
    if (out_size >= 33554432 + 64) tail_kernel<<<1, 64>>>(out);
}

// round 8
// speedup vs baseline: 1.5259x; 1.5259x over previous
#include <cuda_runtime.h>
#include <math.h>

typedef unsigned long long ull;
#define NCTA 128
#define TPB  512
#define PSTRIDE 18   // partials row stride in ull (EVEN -> 16B-aligned vector stores)

// ---- device scratch (static; allocations forbidden) ----
__device__ float g_u[512u*1024u*64u];   // u[t][d][b]
__device__ float g_s[512u*1024u*64u];   // states[t][d][b]
__device__ float g_x[2][1024*64];       // state ping-pong, layout [k][b]
__device__ int   g_len[64];
__device__ unsigned g_bar_count;
__device__ unsigned g_bar_gen;

// ---- packed f32x2 helpers ----
__device__ __forceinline__ ull pack2(float a, float b){ ull r; asm("mov.b64 %0,{%1,%2};":"=l"(r):"f"(a),"f"(b)); return r; }
__device__ __forceinline__ float2 unpk(ull v){ float2 r; asm("mov.b64 {%0,%1},%2;":"=f"(r.x),"=f"(r.y):"l"(v)); return r; }
__device__ __forceinline__ ull ffma2(ull a, ull b, ull c){ ull d; asm("fma.rn.f32x2 %0,%1,%2,%3;":"=l"(d):"l"(a),"l"(b),"l"(c)); return d; }
__device__ __forceinline__ ull add2(ull a, ull b){ ull d; asm("add.rn.f32x2 %0,%1,%2;":"=l"(d):"l"(a),"l"(b)); return d; }

// ---- init ----
__global__ void init_kernel(const float* __restrict__ x0) {
    int idx = blockIdx.x * 256 + threadIdx.x;
    g_x[0][idx] = x0[idx >> 6];
    if (idx < 64) g_len[idx] = 0;
}

// ---- lengths ----
__global__ void len_kernel(const float* __restrict__ emb) {
    int t = blockIdx.x;
    int b = threadIdx.x >> 2, p = threadIdx.x & 3;
    const float* row = emb + ((size_t)t*64 + b)*300;
    float s = 0.f;
    for (int i = p; i < 300; i += 4) s += row[i];
    s += __shfl_xor_sync(0xffffffffu, s, 1);
    s += __shfl_xor_sync(0xffffffffu, s, 2);
    if (p == 0 && s != 0.f) atomicAdd(&g_len[b], 1);
}

// ---- projection: 2 timesteps/block, float4-coalesced global loads ----
__global__ __launch_bounds__(256) void proj_kernel(const float* __restrict__ emb,
                                                   const float* __restrict__ win,
                                                   const float* __restrict__ bias) {
    __align__(16) __shared__ float Es[2][32][66];
    __align__(16) __shared__ ull   Wd[32][66];
    const int tid = threadIdx.x;
    const int tx = tid & 15;          // b-group
    const int ty = tid >> 4;          // d-group
    const int t0 = blockIdx.y * 2;
    const int d0 = blockIdx.x * 64;

    ull acc[2][4][2];
    #pragma unroll
    for (int h = 0; h < 2; ++h)
        #pragma unroll
        for (int i = 0; i < 4; ++i) { acc[h][i][0] = 0ull; acc[h][i][1] = 0ull; }

    for (int k0 = 0; k0 < 300; k0 += 32) {
        // E: 1024 float4 slots, coalesced
        #pragma unroll
        for (int p = 0; p < 4; ++p) {
            int idx = tid + 256*p;
            int h = idx >> 9, rem = idx & 511;
            int b = rem >> 3, kq = rem & 7;
            int k = k0 + 4*kq;
            float4 v = make_float4(0.f, 0.f, 0.f, 0.f);
            if (k + 3 < 300) v = *(const float4*)&emb[((size_t)(t0+h)*64 + b)*300 + k];
            Es[h][4*kq+0][b] = v.x;
            Es[h][4*kq+1][b] = v.y;
            Es[h][4*kq+2][b] = v.z;
            Es[h][4*kq+3][b] = v.w;
        }
        // W: 512 float4 slots, coalesced; store as dup pairs
        #pragma unroll
        for (int p = 0; p < 2; ++p) {
            int idx = tid + 256*p;
            int dl = idx >> 3, kq = idx & 7;
            int k = k0 + 4*kq;
            float4 v = make_float4(0.f, 0.f, 0.f, 0.f);
            if (k + 3 < 300) v = *(const float4*)&win[((size_t)(d0+dl))*300 + k];
            Wd[4*kq+0][dl] = pack2(v.x, v.x);
            Wd[4*kq+1][dl] = pack2(v.y, v.y);
            Wd[4*kq+2][dl] = pack2(v.z, v.z);
            Wd[4*kq+3][dl] = pack2(v.w, v.w);
        }
        __syncthreads();
        #pragma unroll
        for (int kk = 0; kk < 32; ++kk) {
            ulonglong2 wA = *(const ulonglong2*)&Wd[kk][ty*4];
            ulonglong2 wB = *(const ulonglong2*)&Wd[kk][ty*4 + 2];
            #pragma unroll
            for (int h = 0; h < 2; ++h) {
                ull e01 = *(const ull*)&Es[h][kk][tx*4];
                ull e23 = *(const ull*)&Es[h][kk][tx*4 + 2];
                acc[h][0][0] = ffma2(e01, wA.x, acc[h][0][0]); acc[h][0][1] = ffma2(e23, wA.x, acc[h][0][1]);
                acc[h][1][0] = ffma2(e01, wA.y, acc[h][1][0]); acc[h][1][1] = ffma2(e23, wA.y, acc[h][1][1]);
                acc[h][2][0] = ffma2(e01, wB.x, acc[h][2][0]); acc[h][2][1] = ffma2(e23, wB.x, acc[h][2][1]);
                acc[h][3][0] = ffma2(e01, wB.y, acc[h][3][0]); acc[h][3][1] = ffma2(e23, wB.y, acc[h][3][1]);
            }
        }
        __syncthreads();
    }
    #pragma unroll
    for (int h = 0; h < 2; ++h)
        #pragma unroll
        for (int dd = 0; dd < 4; ++dd) {
            int d = d0 + ty*4 + dd;
            float bb = bias[d];
            float2 p0 = unpk(acc[h][dd][0]), p1 = unpk(acc[h][dd][1]);
            float4 o = make_float4(p0.x + bb, p0.y + bb, p1.x + bb, p1.y + bb);
            *(float4*)&g_u[((size_t)(t0+h)*1024 + d)*64 + tx*4] = o;
        }
}

// ---- grid barrier: acq_rel arrive + acquire poll ----
__device__ __forceinline__ void grid_barrier() {
    __syncthreads();
    if (threadIdx.x == 0) {
        unsigned gen;
        asm volatile("ld.acquire.gpu.global.u32 %0, [%1];" : "=r"(gen) : "l"(&g_bar_gen));
        unsigned prev;
        asm volatile("atom.acq_rel.gpu.global.add.u32 %0, [%1], 1;" : "=r"(prev) : "l"(&g_bar_count));
        if (prev == NCTA - 1u) {
            asm volatile("st.relaxed.gpu.global.u32 [%0], %1;" :: "l"(&g_bar_count), "r"(0u));
            asm volatile("st.release.gpu.global.u32 [%0], %1;" :: "l"(&g_bar_gen), "r"(gen + 1u));
        } else {
            unsigned g2;
            do {
                asm volatile("ld.acquire.gpu.global.u32 %0, [%1];" : "=r"(g2) : "l"(&g_bar_gen));
            } while (g2 == gen);
        }
    }
    __syncthreads();
}

// ---- persistent scan: R6 core + per-CTA k-slice rotation ----
__global__ __launch_bounds__(TPB, 1) void scan_kernel(const float* __restrict__ layer_w,
                                                      const float* __restrict__ init_state) {
    extern __shared__ __align__(16) unsigned char dsm[];
    ull* wsm  = (ull*)dsm;                  // 8256 ull = 66048 B
    ull* part = (ull*)(dsm + 66048);        // 512 * PSTRIDE ull = 73728 B

    const int ct   = threadIdx.x;
    const int bq   = ct & 15;
    const int ks   = ct >> 4;               // 0..31
    const int base = blockIdx.x * 8;
    const int kse  = (ks + (int)(blockIdx.x & 31)) & 31;  // rotated k-slice (LTS spread)

    for (int k = ct; k < 1024; k += TPB) {
        #pragma unroll
        for (int r = 0; r < 8; ++r) {
            float w = layer_w[(size_t)(base + r) * 1024 + k];
            wsm[(size_t)k * 8 + r + (k >> 5) * 2] = pack2(w, w);
        }
    }

    const int rr = (ct >> 5) & 7, bp = ct & 31;
    const int dd = base + rr;
    float xo0 = init_state[dd], xo1 = init_state[dd];
    int len0 = 0, len1 = 0;
    if (ct < 256) { len0 = g_len[2*bp]; len1 = g_len[2*bp + 1]; }

    const ull* wbase = wsm + (size_t)kse * 258;   // kse*32*8 + kse*2
    __syncthreads();

    for (int t = 0; t < 512; ++t) {
        const float* xin  = g_x[t & 1];
        float*       xout = g_x[(t & 1) ^ 1];

        ull upre = 0ull;
        if (ct < 256) upre = *(const ull*)&g_u[((size_t)t*1024 + dd)*64 + 2*bp];

        ull acc[16];
        #pragma unroll
        for (int i = 0; i < 16; ++i) acc[i] = 0ull;

        const float* xp = xin + (size_t)(kse * 32) * 64 + bq * 4;

        // 2-stage register double-buffer over 8 chunks of 4 k
        ulonglong2 xva[4], xvb[4];
        #pragma unroll
        for (int j = 0; j < 4; ++j)
            xva[j] = __ldcg((const ulonglong2*)(xp + (size_t)j * 64));

        #pragma unroll
        for (int c = 0; c < 8; ++c) {
            ulonglong2* cur = (c & 1) ? xvb : xva;
            ulonglong2* nxt = (c & 1) ? xva : xvb;
            if (c < 7) {
                #pragma unroll
                for (int j = 0; j < 4; ++j)
                    nxt[j] = __ldcg((const ulonglong2*)(xp + (size_t)((c + 1) * 4 + j) * 64));
            }
            #pragma unroll
            for (int j = 0; j < 4; ++j) {
                const ull* wk = wbase + (size_t)(c * 4 + j) * 8;
                ulonglong2 wa = *(const ulonglong2*)(wk);
                ulonglong2 wb = *(const ulonglong2*)(wk + 2);
                ulonglong2 wc = *(const ulonglong2*)(wk + 4);
                ulonglong2 wd = *(const ulonglong2*)(wk + 6);
                acc[0]  = ffma2(cur[j].x, wa.x, acc[0]);  acc[1]  = ffma2(cur[j].y, wa.x, acc[1]);
                acc[2]  = ffma2(cur[j].x, wa.y, acc[2]);  acc[3]  = ffma2(cur[j].y, wa.y, acc[3]);
                acc[4]  = ffma2(cur[j].x, wb.x, acc[4]);  acc[5]  = ffma2(cur[j].y, wb.x, acc[5]);
                acc[6]  = ffma2(cur[j].x, wb.y, acc[6]);  acc[7]  = ffma2(cur[j].y, wb.y, acc[7]);
                acc[8]  = ffma2(cur[j].x, wc.x, acc[8]);  acc[9]  = ffma2(cur[j].y, wc.x, acc[9]);
                acc[10] = ffma2(cur[j].x, wc.y, acc[10]); acc[11] = ffma2(cur[j].y, wc.y, acc[11]);
                acc[12] = ffma2(cur[j].x, wd.x, acc[12]); acc[13] = ffma2(cur[j].y, wd.x, acc[13]);
                acc[14] = ffma2(cur[j].x, wd.y, acc[14]); acc[15] = ffma2(cur[j].y, wd.y, acc[15]);
            }
        }

        ull* prow = part + (size_t)ct * PSTRIDE;
        #pragma unroll
        for (int i = 0; i < 8; ++i)
            *(ulonglong2*)&prow[2*i] = make_ulonglong2(acc[2*i], acc[2*i+1]);
        __syncthreads();

        if (ct < 256) {
            const int bq2 = bp >> 1, col = rr*2 + (bp & 1);
            ull s0 = upre, s1 = 0ull, s2 = 0ull, s3 = 0ull;
            #pragma unroll
            for (int kss = 0; kss < 32; kss += 4) {
                s0 = add2(s0, part[(size_t)((kss+0)*16 + bq2)*PSTRIDE + col]);
                s1 = add2(s1, part[(size_t)((kss+1)*16 + bq2)*PSTRIDE + col]);
                s2 = add2(s2, part[(size_t)((kss+2)*16 + bq2)*PSTRIDE + col]);
                s3 = add2(s3, part[(size_t)((kss+3)*16 + bq2)*PSTRIDE + col]);
            }
            ull s = add2(add2(s0, s1), add2(s2, s3));

            float2 a = unpk(s);
            float n0 = 0.5f * tanhf(a.x) + 0.5f * xo0;
            float n1 = 0.5f * tanhf(a.y) + 0.5f * xo1;
            if (t >= len0) n0 = 0.f;
            if (t >= len1) n1 = 0.f;
            xo0 = n0; xo1 = n1;

            __stcg((float2*)(xout + (size_t)dd*64 + 2*bp), make_float2(n0, n1));
            *(float2*)&g_s[((size_t)t*1024 + dd)*64 + 2*bp] = make_float2(n0, n1);
        }
        grid_barrier();
    }
}

// ---- transpose g_s[t][d][b] -> out[b][t][d] ----
__global__ __launch_bounds__(256) void trans_kernel(float* __restrict__ out) {
    __shared__ float ts[64][65];
    const int t  = blockIdx.y;
    const int d0 = blockIdx.x * 64;
    const int tid = threadIdx.x;
    #pragma unroll
    for (int j = 0; j < 16; ++j) {
        int idx = j*256 + tid;
        int dl = idx >> 6, b = idx & 63;
        ts[dl][b] = g_s[(((size_t)t << 10) + d0 + dl)*64 + b];
    }
    __syncthreads();
    #pragma unroll
    for (int j = 0; j < 16; ++j) {
        int idx = j*256 + tid;
        int b = idx >> 6, dl = idx & 63;
        out[((size_t)b*512 + t)*1024 + d0 + dl] = ts[dl][b];
    }
}

__global__ void tail_kernel(float* out) {
    int b = threadIdx.x;
    if (b < 64) out[33554432u + b] = (float)g_len[b];
}

extern "C" void kernel_launch(void* const* d_in, const int* in_sizes, int n_in,
                              void* d_out, int out_size) {
    const float* emb  = (const float*)d_in[0];
    const float* win  = (const float*)d_in[1];
    const float* lw   = (const float*)d_in[2];
    const float* bias = (const float*)d_in[3];
    const float* x0   = (const float*)d_in[4];
    float* out = (float*)d_out;

    static int smem_set = 0;
    if (!smem_set) {
        cudaFuncSetAttribute(scan_kernel, cudaFuncAttributeMaxDynamicSharedMemorySize, 139776);
        smem_set = 1;
    }

    init_kernel<<<256, 256>>>(x0);
    len_kernel<<<512, 256>>>(emb);
    proj_kernel<<<dim3(16, 256), 256>>>(emb, win, bias);
    scan_kernel<<<NCTA, TPB, 139776>>>(lw, x0);
    trans_kernel<<<dim3(16, 512), 256>>>(out);
    if (out_size >= 33554432 + 64) tail_kernel<<<1, 64>>>(out);
}